// round 8
// baseline (speedup 1.0000x reference)
#include <cuda_runtime.h>
#include <cstdint>
#include <cstddef>

#define NORB   9
#define NATOMS 384
#define NEDGES 6144
#define NKP    4
#define ALLN   (NATOMS * NORB)              // 3456
#define NFEAT  58
#define NCPLX  ((size_t)NKP * ALLN * ALLN)  // 47,775,744 = 4*3456*3456
#define TWO_PI 6.283185307179586f

#define NCHUNK       6
#define CHUNK_FLOATS 5184                   // 20736 B = 1.5 matrix rows
#define CHUNK_BYTES  (CHUNK_FLOATS * 4)
#define MAXE         256                    // entry-list capacity per CTA

// Static feature -> (row, col, factor) maps for upper-tri orbital pairs
// l = [0,1,2], dims = [1,3,5], offsets = [0,1,4]
__constant__ unsigned char cROWS[NFEAT] = {
    0,
    0,0,0,
    0,0,0,0,0,
    1,1,1,2,2,2,3,3,3,
    1,1,1,1,1,2,2,2,2,2,3,3,3,3,3,
    4,4,4,4,4,5,5,5,5,5,6,6,6,6,6,7,7,7,7,7,8,8,8,8,8
};
__constant__ unsigned char cCOLS[NFEAT] = {
    0,
    1,2,3,
    4,5,6,7,8,
    1,2,3,1,2,3,1,2,3,
    4,5,6,7,8,4,5,6,7,8,4,5,6,7,8,
    4,5,6,7,8,4,5,6,7,8,4,5,6,7,8,4,5,6,7,8,4,5,6,7,8
};
__constant__ float cFACS[NFEAT] = {
    0.5f,
    1.f,1.f,1.f,
    1.f,1.f,1.f,1.f,1.f,
    0.5f,0.5f,0.5f,0.5f,0.5f,0.5f,0.5f,0.5f,0.5f,
    1.f,1.f,1.f,1.f,1.f,1.f,1.f,1.f,1.f,1.f,1.f,1.f,1.f,1.f,1.f,
    0.5f,0.5f,0.5f,0.5f,0.5f,0.5f,0.5f,0.5f,0.5f,0.5f,0.5f,0.5f,0.5f,
    0.5f,0.5f,0.5f,0.5f,0.5f,0.5f,0.5f,0.5f,0.5f,0.5f,0.5f,0.5f
};

__device__ __forceinline__ uint32_t smem_u32(const void* p) {
    uint32_t a;
    asm("{ .reg .u64 t; cvta.to.shared.u64 t, %1; cvt.u32.u64 %0, t; }"
        : "=r"(a) : "l"(p));
    return a;
}

// ---- Single fused kernel ----
// CTA = (ai, k) exclusively owns the contiguous 124,416-byte slab
// out[k][ai*9 .. ai*9+9][*]. It scans the edge list for incident edges,
// then produces the slab in 6 double-buffered smem chunks: zero chunk,
// accumulate contributions (smem atomics), cp.async.bulk store to GMEM.
// TMA drains overlap the next chunk's compute. No global atomics, no
// separate zero-fill, no prep kernels.
__global__ __launch_bounds__(256) void hr2hk_chunked(
    const float* __restrict__ hop,     // [E, 58]
    const float* __restrict__ ons,     // [N, 58]
    const float* __restrict__ kpts,    // [4, 3]
    const int*   __restrict__ eidx,    // [2, E]
    const int*   __restrict__ eshift,  // [E, 3]
    float*       __restrict__ out)     // [4, 3456, 3456] float32 (real part)
{
    __shared__ __align__(16) float buf[2][CHUNK_FLOATS];   // 41,472 B
    __shared__ int   sE  [MAXE];   // edge id, or -1 for onsite
    __shared__ int   sCol[MAXE];   // column base = other_atom * 9
    __shared__ float sPh [MAXE];   // cos(2*pi k.R)  (sign bit of sE... no: )
    __shared__ unsigned char sTr[MAXE];  // 1 = transposed (B^H side)
    __shared__ int   sCnt;

    const int b   = blockIdx.x;
    const int k   = b & 3;
    const int ai  = b >> 2;
    const int tid = threadIdx.x;

    const float kx = kpts[k * 3 + 0];
    const float ky = kpts[k * 3 + 1];
    const float kz = kpts[k * 3 + 2];

    if (tid == 0) sCnt = 2;   // slots 0,1 reserved for onsite (below)
    __syncthreads();

    // Onsite entries: block + its transpose (orbital-diagonal 0.5*2 = 1).
    if (tid == 0) {
        sE[0] = -1; sCol[0] = ai * NORB; sPh[0] = 1.f; sTr[0] = 0;
        sE[1] = -1; sCol[1] = ai * NORB; sPh[1] = 1.f; sTr[1] = 1;
    }

    // Scan the edge list for edges incident to ai (L2-broadcast reads).
    for (int e = tid; e < NEDGES; e += 256) {
        const int i = eidx[e];
        const int j = eidx[NEDGES + e];
        const bool mo = (i == ai);    // out-edge: B rows at ai
        const bool mi = (j == ai);    // in-edge:  B^H rows at ai
        if (!(mo | mi)) continue;
        const float d = kx * (float)eshift[e * 3 + 0]
                      + ky * (float)eshift[e * 3 + 1]
                      + kz * (float)eshift[e * 3 + 2];
        const float ph = __cosf(TWO_PI * d);
        if (mo) {
            int p = atomicAdd(&sCnt, 1);
            if (p < MAXE) { sE[p] = e; sCol[p] = j * NORB; sPh[p] = ph; sTr[p] = 0; }
        }
        if (mi) {
            int p = atomicAdd(&sCnt, 1);
            if (p < MAXE) { sE[p] = e; sCol[p] = i * NORB; sPh[p] = ph; sTr[p] = 1; }
        }
    }
    __syncthreads();

    const int cnt   = min(sCnt, MAXE);
    const int total = cnt * NFEAT;

    float* __restrict__ slab =
        out + (size_t)k * ALLN * ALLN + (size_t)(ai * NORB) * ALLN;

    // Chunked production pipeline.
    for (int s = 0; s < NCHUNK; ++s) {
        float* cb = buf[s & 1];

        // Reuse guard: the TMA store issued for this buffer (chunk s-2)
        // must have finished reading it.
        if (s >= 2 && tid == 0)
            asm volatile("cp.async.bulk.wait_group 1;" ::: "memory");
        __syncthreads();

        // Zero the chunk (324 float4 over 256 threads).
        float4* c4 = (float4*)cb;
        #pragma unroll
        for (int i = tid; i < CHUNK_FLOATS / 4; i += 256)
            c4[i] = make_float4(0.f, 0.f, 0.f, 0.f);
        __syncthreads();

        // Accumulate all (entry, feature) work items landing in this chunk.
        const int lo = s * CHUNK_FLOATS, hi = lo + CHUNK_FLOATS;
        for (int it = tid; it < total; it += 256) {
            const int en = it / NFEAT;
            const int f  = it - en * NFEAT;
            int ro = cROWS[f], co = cCOLS[f];
            if (sTr[en]) { const int t = ro; ro = co; co = t; }
            const int off = ro * ALLN + sCol[en] + co;   // slab element offset
            if (off < lo || off >= hi) continue;
            const int e = sE[en];
            const float* __restrict__ src =
                (e >= 0) ? (hop + (size_t)e * NFEAT) : (ons + (size_t)ai * NFEAT);
            const float v = cFACS[f] * src[f] * sPh[en];
            atomicAdd(&cb[off - lo], v);
        }
        __syncthreads();

        // Store chunk to GMEM via bulk async copy; drain overlaps next chunk.
        if (tid == 0) {
            asm volatile("fence.proxy.async.shared::cta;" ::: "memory");
            asm volatile(
                "cp.async.bulk.global.shared::cta.bulk_group [%0], [%1], %2;"
                :: "l"((char*)slab + (size_t)s * CHUNK_BYTES),
                   "r"(smem_u32(cb)), "r"(CHUNK_BYTES)
                : "memory");
            asm volatile("cp.async.bulk.commit_group;" ::: "memory");
        }
        __syncthreads();
    }

    // All bulk stores must complete before kernel exit.
    if (tid == 0)
        asm volatile("cp.async.bulk.wait_group 0;" ::: "memory");
}

// ---- complex64 fallback path (kept for safety; unused for f32 output) ----
__global__ __launch_bounds__(256, 8) void hr2hk_scatter_cplx(
    const float* __restrict__ hop,
    const float* __restrict__ ons,
    const float* __restrict__ kpts,
    const int*   __restrict__ eidx,
    const int*   __restrict__ eshift,
    float*       __restrict__ out)
{
    const int w = blockIdx.x;
    const int t = threadIdx.x;
    if (t >= NFEAT * NKP) return;
    const int f = t >> 2;
    const int k = t & 3;
    const bool is_edge = (w < NEDGES);

    int ai, aj;
    float pre, pim;
    if (is_edge) {
        ai = eidx[w];
        aj = eidx[NEDGES + w];
        const float d = kpts[k * 3 + 0] * (float)eshift[w * 3 + 0]
                      + kpts[k * 3 + 1] * (float)eshift[w * 3 + 1]
                      + kpts[k * 3 + 2] * (float)eshift[w * 3 + 2];
        float s, c;
        __sincosf(TWO_PI * d, &s, &c);
        pre = c; pim = -s;
    } else {
        ai = w - NEDGES; aj = ai; pre = 1.f; pim = 0.f;
    }
    if ((unsigned)ai >= NATOMS || (unsigned)aj >= NATOMS) return;

    const float* __restrict__ src =
        is_edge ? (hop + (size_t)w * NFEAT)
                : (ons + (size_t)(w - NEDGES) * NFEAT);
    const float val = cFACS[f] * src[f];
    const float re = val * pre, im = val * pim;
    const int r = ai * NORB + (int)cROWS[f];
    const int c = aj * NORB + (int)cCOLS[f];
    const size_t kbase = (size_t)k * ALLN * ALLN;
    float* p0 = out + 2 * (kbase + (size_t)r * ALLN + c);
    float* p1 = out + 2 * (kbase + (size_t)c * ALLN + r);
    atomicAdd(p0 + 0, re);
    atomicAdd(p0 + 1, im);
    atomicAdd(p1 + 0, re);
    atomicAdd(p1 + 1, -im);
}

__global__ void hr2hk_zero(uint4* __restrict__ out, size_t n_u4) {
    for (size_t i = (size_t)blockIdx.x * blockDim.x + threadIdx.x;
         i < n_u4; i += (size_t)gridDim.x * blockDim.x)
        out[i] = make_uint4(0u, 0u, 0u, 0u);
}

extern "C" void kernel_launch(void* const* d_in, const int* in_sizes, int n_in,
                              void* d_out, int out_size) {
    // Identify inputs by (pairwise-distinct) element counts, not position.
    const float* hop    = nullptr;
    const float* ons    = nullptr;
    const float* kpts   = nullptr;
    const int*   eidx   = nullptr;
    const int*   eshift = nullptr;

    for (int i = 0; i < n_in; ++i) {
        switch (in_sizes[i]) {
            case NEDGES * NFEAT: hop    = (const float*)d_in[i]; break;  // 356352
            case NATOMS * NFEAT: ons    = (const float*)d_in[i]; break;  // 22272
            case NKP * 3:        kpts   = (const float*)d_in[i]; break;  // 12
            case 2 * NEDGES:     eidx   = (const int*)d_in[i];   break;  // 12288
            case NEDGES * 3:     eshift = (const int*)d_in[i];   break;  // 18432
            default: break;
        }
    }
    if (!hop || !ons || !kpts || !eidx || !eshift) return;

    if ((long long)out_size == (long long)NCPLX) {
        // float32 real-part output: single fused kernel, write-once output.
        hr2hk_chunked<<<NATOMS * NKP, 256>>>(
            hop, ons, kpts, eidx, eshift, (float*)d_out);
    } else if ((long long)out_size == 2LL * (long long)NCPLX) {
        hr2hk_zero<<<8192, 256>>>((uint4*)d_out, NCPLX * 8 / 16);
        hr2hk_scatter_cplx<<<NEDGES + NATOMS, 256>>>(
            hop, ons, kpts, eidx, eshift, (float*)d_out);
    }
}

// round 9
// speedup vs baseline: 3.6558x; 3.6558x over previous
#include <cuda_runtime.h>
#include <cstdint>
#include <cstddef>

#define NORB   9
#define NATOMS 384
#define NEDGES 6144
#define NKP    4
#define ALLN   (NATOMS * NORB)              // 3456
#define NFEAT  58
#define NCPLX  ((size_t)NKP * ALLN * ALLN)  // 47,775,744 = 4*3456*3456
#define NPAIR  (NATOMS * NATOMS)            // 147456
#define NSLOT  (2 * NEDGES + NATOMS)        // 12672
#define TWO_PI 6.283185307179586f

// Feature factors (0.5 on l-diagonal orbital pairs, else 1.0)
__constant__ float cFACS[NFEAT] = {
    0.5f,
    1.f,1.f,1.f,
    1.f,1.f,1.f,1.f,1.f,
    0.5f,0.5f,0.5f,0.5f,0.5f,0.5f,0.5f,0.5f,0.5f,
    1.f,1.f,1.f,1.f,1.f,1.f,1.f,1.f,1.f,1.f,1.f,1.f,1.f,1.f,1.f,
    0.5f,0.5f,0.5f,0.5f,0.5f,0.5f,0.5f,0.5f,0.5f,0.5f,0.5f,0.5f,0.5f,
    0.5f,0.5f,0.5f,0.5f,0.5f,0.5f,0.5f,0.5f,0.5f,0.5f,0.5f,0.5f
};

// feature index for upper-pattern position (r,c) of the 9x9 block, else -1.
// l=[0,1,2], dims=[1,3,5], offsets=[0,1,4]: (0,*)->0..8, (1..3,1..3)->9..17,
// (1..3,4..8)->18..32, (4..8,4..8)->33..57.
__device__ __forceinline__ int fmap(int r, int c) {
    if (r == 0) return c;
    if (r <= 3) {
        if (c >= 4) return 18 + (r - 1) * 5 + (c - 4);
        if (c >= 1) return 9 + (r - 1) * 3 + (c - 1);
        return -1;
    }
    return (c >= 4) ? (33 + (r - 4) * 5 + (c - 4)) : -1;
}

// ---- static scratch (no allocation) ----
__device__ int   g_head[NPAIR];                 // pair (a,b) -> first slot, -1
__device__ int   g_next[NSLOT];                 // chain links
__device__ float g_comp[NKP][NSLOT][81];        // 16.4 MB block values

// Reset the pair->chain heads (147456 = 576*256 exact).
__global__ void k_zero_head() {
    g_head[blockIdx.x * 256 + threadIdx.x] = -1;
}

// Push every contribution slot onto its (rowblock, colblock) chain.
// slot e          : edge e direct   -> pair (i, j)
// slot NEDGES+e   : edge e transpose-> pair (j, i)
// slot 2*NEDGES+a : onsite atom a   -> pair (a, a)
__global__ void k_chain(const int* __restrict__ eidx) {
    const int t = blockIdx.x * blockDim.x + threadIdx.x;
    if (t < NEDGES) {
        const int i = eidx[t], j = eidx[NEDGES + t];
        if ((unsigned)i < NATOMS && (unsigned)j < NATOMS) {
            g_next[t]          = atomicExch(&g_head[i * NATOMS + j], t);
            g_next[NEDGES + t] = atomicExch(&g_head[j * NATOMS + i], NEDGES + t);
        }
    } else if (t < NEDGES + NATOMS) {
        const int a = t - NEDGES;
        g_next[2 * NEDGES + a] = atomicExch(&g_head[a * NATOMS + a], 2 * NEDGES + a);
    }
}

// Compute all 9x9 block values into g_comp. One block per slot, 81 active
// threads, all 4 k-points per thread (feature loads amortized).
__global__ __launch_bounds__(96) void k_blocks(
    const float* __restrict__ hop,     // [E, 58]
    const float* __restrict__ ons,     // [N, 58]
    const float* __restrict__ kpts,    // [4, 3]
    const int*   __restrict__ eshift)  // [E, 3]
{
    __shared__ float sph[NKP];
    const int slot = blockIdx.x;
    const int tid  = threadIdx.x;

    int e; const float* __restrict__ src; int useT0, useT1;
    if (slot < NEDGES) {                       // direct: B at (i,j)
        e = slot; src = hop + (size_t)e * NFEAT; useT0 = 1; useT1 = 0;
    } else if (slot < 2 * NEDGES) {            // transpose: B^T at (j,i)
        e = slot - NEDGES; src = hop + (size_t)e * NFEAT; useT0 = 0; useT1 = 1;
    } else {                                   // onsite: B + B^T at (a,a)
        e = -1; src = ons + (size_t)(slot - 2 * NEDGES) * NFEAT; useT0 = 1; useT1 = 1;
    }

    if (tid < NKP) {
        float p = 1.f;
        if (e >= 0) {
            const float d = kpts[tid * 3 + 0] * (float)eshift[e * 3 + 0]
                          + kpts[tid * 3 + 1] * (float)eshift[e * 3 + 1]
                          + kpts[tid * 3 + 2] * (float)eshift[e * 3 + 2];
            p = __cosf(TWO_PI * d);            // Re[exp(-2*pi*i k.R)]
        }
        sph[tid] = p;
    }
    __syncthreads();
    if (tid >= 81) return;

    const int orow = tid / 9, ocol = tid - orow * 9;
    const int f0 = fmap(orow, ocol);           // direct pattern
    const int f1 = fmap(ocol, orow);           // transposed pattern
    float base = 0.f;
    if (useT0 && f0 >= 0) base += cFACS[f0] * src[f0];
    if (useT1 && f1 >= 0) base += cFACS[f1] * src[f1];

    #pragma unroll
    for (int k = 0; k < NKP; ++k)
        g_comp[k][slot][tid] = base * sph[k];
}

// Streaming writer: one float4 per thread (exact grid), composing zeros and
// chained block values at write time. Every output byte written exactly once.
__global__ __launch_bounds__(256) void k_write(float4* __restrict__ out) {
    const int U4K  = ALLN * ALLN / 4;          // 2,985,984 float4 per k
    const int U4R  = ALLN / 4;                 // 864 float4 per row
    const int idx  = blockIdx.x * 256 + threadIdx.x;

    const int kk  = idx / U4K;
    const int rem = idx - kk * U4K;
    const int row = rem / U4R;
    const int c4  = rem - row * U4R;
    const int rb  = row / NORB;
    const int orow = row - rb * NORB;
    const int col0 = c4 * 4;
    const int cb0  = col0 / NORB;
    const int oc0  = col0 - cb0 * NORB;

    const int* __restrict__ hrow = g_head + rb * NATOMS;
    int cb_c = cb0;
    int h_c  = hrow[cb0];

    float o[4];
    #pragma unroll
    for (int u = 0; u < 4; ++u) {
        int oc = oc0 + u, cb = cb0;
        if (oc >= NORB) { oc -= NORB; cb = cb0 + 1; }
        if (cb != cb_c) { cb_c = cb; h_c = hrow[cb]; }
        int h = h_c;
        float s = 0.f;
        while (h >= 0) {                       // avg chain length ~1, 91% empty
            s += g_comp[kk][h][orow * NORB + oc];
            h  = g_next[h];
        }
        o[u] = s;
    }
    out[idx] = make_float4(o[0], o[1], o[2], o[3]);
}

// ---- complex64 fallback (unused for the f32 output; kept for safety) ----
__constant__ unsigned char cROWS[NFEAT] = {
    0, 0,0,0, 0,0,0,0,0,
    1,1,1,2,2,2,3,3,3,
    1,1,1,1,1,2,2,2,2,2,3,3,3,3,3,
    4,4,4,4,4,5,5,5,5,5,6,6,6,6,6,7,7,7,7,7,8,8,8,8,8
};
__constant__ unsigned char cCOLS[NFEAT] = {
    0, 1,2,3, 4,5,6,7,8,
    1,2,3,1,2,3,1,2,3,
    4,5,6,7,8,4,5,6,7,8,4,5,6,7,8,
    4,5,6,7,8,4,5,6,7,8,4,5,6,7,8,4,5,6,7,8,4,5,6,7,8
};

__global__ void hr2hk_zero(uint4* __restrict__ out, size_t n_u4) {
    for (size_t i = (size_t)blockIdx.x * blockDim.x + threadIdx.x;
         i < n_u4; i += (size_t)gridDim.x * blockDim.x)
        out[i] = make_uint4(0u, 0u, 0u, 0u);
}

__global__ __launch_bounds__(256, 8) void hr2hk_scatter_cplx(
    const float* __restrict__ hop, const float* __restrict__ ons,
    const float* __restrict__ kpts, const int* __restrict__ eidx,
    const int* __restrict__ eshift, float* __restrict__ out)
{
    const int w = blockIdx.x;
    const int t = threadIdx.x;
    if (t >= NFEAT * NKP) return;
    const int f = t >> 2;
    const int k = t & 3;
    const bool is_edge = (w < NEDGES);

    int ai, aj;
    float pre, pim;
    if (is_edge) {
        ai = eidx[w];
        aj = eidx[NEDGES + w];
        const float d = kpts[k * 3 + 0] * (float)eshift[w * 3 + 0]
                      + kpts[k * 3 + 1] * (float)eshift[w * 3 + 1]
                      + kpts[k * 3 + 2] * (float)eshift[w * 3 + 2];
        float s, c;
        __sincosf(TWO_PI * d, &s, &c);
        pre = c; pim = -s;
    } else {
        ai = w - NEDGES; aj = ai; pre = 1.f; pim = 0.f;
    }
    if ((unsigned)ai >= NATOMS || (unsigned)aj >= NATOMS) return;

    const float* __restrict__ src =
        is_edge ? (hop + (size_t)w * NFEAT)
                : (ons + (size_t)(w - NEDGES) * NFEAT);
    const float val = cFACS[f] * src[f];
    const float re = val * pre, im = val * pim;
    const int r = ai * NORB + (int)cROWS[f];
    const int c = aj * NORB + (int)cCOLS[f];
    const size_t kbase = (size_t)k * ALLN * ALLN;
    float* p0 = out + 2 * (kbase + (size_t)r * ALLN + c);
    float* p1 = out + 2 * (kbase + (size_t)c * ALLN + r);
    atomicAdd(p0 + 0, re);
    atomicAdd(p0 + 1, im);
    atomicAdd(p1 + 0, re);
    atomicAdd(p1 + 1, -im);
}

extern "C" void kernel_launch(void* const* d_in, const int* in_sizes, int n_in,
                              void* d_out, int out_size) {
    // Identify inputs by (pairwise-distinct) element counts, not position.
    const float* hop    = nullptr;
    const float* ons    = nullptr;
    const float* kpts   = nullptr;
    const int*   eidx   = nullptr;
    const int*   eshift = nullptr;

    for (int i = 0; i < n_in; ++i) {
        switch (in_sizes[i]) {
            case NEDGES * NFEAT: hop    = (const float*)d_in[i]; break;  // 356352
            case NATOMS * NFEAT: ons    = (const float*)d_in[i]; break;  // 22272
            case NKP * 3:        kpts   = (const float*)d_in[i]; break;  // 12
            case 2 * NEDGES:     eidx   = (const int*)d_in[i];   break;  // 12288
            case NEDGES * 3:     eshift = (const int*)d_in[i];   break;  // 18432
            default: break;
        }
    }
    if (!hop || !ons || !kpts || !eidx || !eshift) return;

    if ((long long)out_size == (long long)NCPLX) {
        // f32 real-part output: compact blocks + chains, then streaming write.
        k_zero_head<<<NPAIR / 256, 256>>>();
        k_chain<<<(NEDGES + NATOMS + 255) / 256, 256>>>(eidx);
        k_blocks<<<NSLOT, 96>>>(hop, ons, kpts, eshift);
        k_write<<<(int)(NCPLX / 4 / 256), 256>>>((float4*)d_out);
    } else if ((long long)out_size == 2LL * (long long)NCPLX) {
        hr2hk_zero<<<8192, 256>>>((uint4*)d_out, NCPLX * 8 / 16);
        hr2hk_scatter_cplx<<<NEDGES + NATOMS, 256>>>(
            hop, ons, kpts, eidx, eshift, (float*)d_out);
    }
}

// round 10
// speedup vs baseline: 4.5496x; 1.2445x over previous
#include <cuda_runtime.h>
#include <cstdint>
#include <cstddef>

#define NORB   9
#define NATOMS 384
#define NEDGES 6144
#define NKP    4
#define ALLN   (NATOMS * NORB)              // 3456
#define NFEAT  58
#define NCPLX  ((size_t)NKP * ALLN * ALLN)  // 47,775,744 = 4*3456*3456
#define NPAIR  (NATOMS * NATOMS)            // 147456
#define NSLOT  (2 * NEDGES + NATOMS)        // 12672
#define TWO_PI 6.283185307179586f

// Feature factors (0.5 on l-diagonal orbital pairs, else 1.0)
__constant__ float cFACS[NFEAT] = {
    0.5f,
    1.f,1.f,1.f,
    1.f,1.f,1.f,1.f,1.f,
    0.5f,0.5f,0.5f,0.5f,0.5f,0.5f,0.5f,0.5f,0.5f,
    1.f,1.f,1.f,1.f,1.f,1.f,1.f,1.f,1.f,1.f,1.f,1.f,1.f,1.f,1.f,
    0.5f,0.5f,0.5f,0.5f,0.5f,0.5f,0.5f,0.5f,0.5f,0.5f,0.5f,0.5f,0.5f,
    0.5f,0.5f,0.5f,0.5f,0.5f,0.5f,0.5f,0.5f,0.5f,0.5f,0.5f,0.5f
};

// feature index for upper-pattern position (r,c) of the 9x9 block, else -1.
// l=[0,1,2], dims=[1,3,5], offsets=[0,1,4].
__device__ __forceinline__ int fmap(int r, int c) {
    if (r == 0) return c;
    if (r <= 3) {
        if (c >= 4) return 18 + (r - 1) * 5 + (c - 4);
        if (c >= 1) return 9 + (r - 1) * 3 + (c - 1);
        return -1;
    }
    return (c >= 4) ? (33 + (r - 4) * 5 + (c - 4)) : -1;
}

// ---- static scratch (no allocation) ----
__device__ int g_head[NPAIR];   // pair (a,b) -> first slot, -1
__device__ int g_next[NSLOT];   // chain links

// Reset the pair->chain heads (147456 = 576*256 exact).
__global__ void k_zero_head() {
    g_head[blockIdx.x * 256 + threadIdx.x] = -1;
}

// Push every contribution slot onto its (rowblock, colblock) chain.
// slot e          : edge e direct    -> pair (i, j)
// slot NEDGES+e   : edge e transpose -> pair (j, i)
// slot 2*NEDGES+a : onsite atom a    -> pair (a, a)
__global__ void k_chain(const int* __restrict__ eidx) {
    const int t = blockIdx.x * blockDim.x + threadIdx.x;
    if (t < NEDGES) {
        const int i = eidx[t], j = eidx[NEDGES + t];
        if ((unsigned)i < NATOMS && (unsigned)j < NATOMS) {
            g_next[t]          = atomicExch(&g_head[i * NATOMS + j], t);
            g_next[NEDGES + t] = atomicExch(&g_head[j * NATOMS + i], NEDGES + t);
        }
    } else if (t < NEDGES + NATOMS) {
        const int a = t - NEDGES;
        g_next[2 * NEDGES + a] = atomicExch(&g_head[a * NATOMS + a], 2 * NEDGES + a);
    }
}

// One warp per atom pair: walk the pair's chain, compute the summed real
// 9x9 block for all 4 k-points in registers, plain-store into the pair's
// exclusive output region. No atomics: each output element has exactly one
// producer warp, and the memset (earlier in stream) supplied the zeros.
__global__ __launch_bounds__(256) void k_pairs(
    const float* __restrict__ hop,     // [E, 58]
    const float* __restrict__ ons,     // [N, 58]
    const float* __restrict__ kpts,    // [4, 3]
    const int*   __restrict__ eshift,  // [E, 3]
    float*       __restrict__ out)     // [4, 3456, 3456] float32 (real part)
{
    const int gw   = (blockIdx.x * 256 + threadIdx.x) >> 5;   // global warp id
    const int lane = threadIdx.x & 31;
    if (gw >= NPAIR) return;

    int h = g_head[gw];
    if (h < 0) return;                 // 91.4% of warps exit here

    const int rb = gw / NATOMS;        // row atom block
    const int cb = gw - rb * NATOMS;   // col atom block

    // Per-lane positions: pos = lane, lane+32, lane+64 (pos < 81).
    int r0[3], c0[3], f0[3], f1[3];
    #pragma unroll
    for (int u = 0; u < 3; ++u) {
        const int pos = lane + u * 32;
        if (pos < 81) {
            r0[u] = pos / 9; c0[u] = pos - r0[u] * 9;
            f0[u] = fmap(r0[u], c0[u]);    // direct pattern
            f1[u] = fmap(c0[u], r0[u]);    // transposed pattern
        } else { f0[u] = f1[u] = -1; r0[u] = c0[u] = 0; }
    }

    float acc[NKP][3] = {};

    while (h >= 0) {
        int e; const float* __restrict__ src; bool d0, d1;
        if (h < NEDGES)            { e = h;          src = hop + (size_t)e * NFEAT; d0 = true;  d1 = false; }
        else if (h < 2 * NEDGES)   { e = h - NEDGES; src = hop + (size_t)e * NFEAT; d0 = false; d1 = true;  }
        else                       { e = -1;         src = ons + (size_t)(h - 2 * NEDGES) * NFEAT; d0 = d1 = true; }

        float ph[NKP];
        if (e >= 0) {
            const float sx = (float)eshift[e * 3 + 0];
            const float sy = (float)eshift[e * 3 + 1];
            const float sz = (float)eshift[e * 3 + 2];
            #pragma unroll
            for (int k = 0; k < NKP; ++k) {
                const float d = kpts[k * 3 + 0] * sx
                              + kpts[k * 3 + 1] * sy
                              + kpts[k * 3 + 2] * sz;
                ph[k] = __cosf(TWO_PI * d);     // Re[exp(-2*pi*i k.R)]
            }
        } else {
            #pragma unroll
            for (int k = 0; k < NKP; ++k) ph[k] = 1.f;
        }

        #pragma unroll
        for (int u = 0; u < 3; ++u) {
            float base = 0.f;
            if (d0 && f0[u] >= 0) base += cFACS[f0[u]] * src[f0[u]];
            if (d1 && f1[u] >= 0) base += cFACS[f1[u]] * src[f1[u]];
            #pragma unroll
            for (int k = 0; k < NKP; ++k) acc[k][u] += base * ph[k];
        }

        h = g_next[h];
    }

    // Plain stores into the pair's exclusive 9x9 region per k.
    float* __restrict__ obase = out + (size_t)(rb * NORB) * ALLN + cb * NORB;
    #pragma unroll
    for (int u = 0; u < 3; ++u) {
        const int pos = lane + u * 32;
        if (pos >= 81) break;
        const size_t off = (size_t)r0[u] * ALLN + c0[u];
        #pragma unroll
        for (int k = 0; k < NKP; ++k)
            obase[(size_t)k * ALLN * ALLN + off] = acc[k][u];
    }
}

// ---- complex64 fallback (unused for the f32 output; kept for safety) ----
__constant__ unsigned char cROWS[NFEAT] = {
    0, 0,0,0, 0,0,0,0,0,
    1,1,1,2,2,2,3,3,3,
    1,1,1,1,1,2,2,2,2,2,3,3,3,3,3,
    4,4,4,4,4,5,5,5,5,5,6,6,6,6,6,7,7,7,7,7,8,8,8,8,8
};
__constant__ unsigned char cCOLS[NFEAT] = {
    0, 1,2,3, 4,5,6,7,8,
    1,2,3,1,2,3,1,2,3,
    4,5,6,7,8,4,5,6,7,8,4,5,6,7,8,
    4,5,6,7,8,4,5,6,7,8,4,5,6,7,8,4,5,6,7,8,4,5,6,7,8
};

__global__ void hr2hk_zero(uint4* __restrict__ out, size_t n_u4) {
    for (size_t i = (size_t)blockIdx.x * blockDim.x + threadIdx.x;
         i < n_u4; i += (size_t)gridDim.x * blockDim.x)
        out[i] = make_uint4(0u, 0u, 0u, 0u);
}

__global__ __launch_bounds__(256, 8) void hr2hk_scatter_cplx(
    const float* __restrict__ hop, const float* __restrict__ ons,
    const float* __restrict__ kpts, const int* __restrict__ eidx,
    const int* __restrict__ eshift, float* __restrict__ out)
{
    const int w = blockIdx.x;
    const int t = threadIdx.x;
    if (t >= NFEAT * NKP) return;
    const int f = t >> 2;
    const int k = t & 3;
    const bool is_edge = (w < NEDGES);

    int ai, aj;
    float pre, pim;
    if (is_edge) {
        ai = eidx[w];
        aj = eidx[NEDGES + w];
        const float d = kpts[k * 3 + 0] * (float)eshift[w * 3 + 0]
                      + kpts[k * 3 + 1] * (float)eshift[w * 3 + 1]
                      + kpts[k * 3 + 2] * (float)eshift[w * 3 + 2];
        float s, c;
        __sincosf(TWO_PI * d, &s, &c);
        pre = c; pim = -s;
    } else {
        ai = w - NEDGES; aj = ai; pre = 1.f; pim = 0.f;
    }
    if ((unsigned)ai >= NATOMS || (unsigned)aj >= NATOMS) return;

    const float* __restrict__ src =
        is_edge ? (hop + (size_t)w * NFEAT)
                : (ons + (size_t)(w - NEDGES) * NFEAT);
    const float val = cFACS[f] * src[f];
    const float re = val * pre, im = val * pim;
    const int r = ai * NORB + (int)cROWS[f];
    const int c = aj * NORB + (int)cCOLS[f];
    const size_t kbase = (size_t)k * ALLN * ALLN;
    float* p0 = out + 2 * (kbase + (size_t)r * ALLN + c);
    float* p1 = out + 2 * (kbase + (size_t)c * ALLN + r);
    atomicAdd(p0 + 0, re);
    atomicAdd(p0 + 1, im);
    atomicAdd(p1 + 0, re);
    atomicAdd(p1 + 1, -im);
}

extern "C" void kernel_launch(void* const* d_in, const int* in_sizes, int n_in,
                              void* d_out, int out_size) {
    // Identify inputs by (pairwise-distinct) element counts, not position.
    const float* hop    = nullptr;
    const float* ons    = nullptr;
    const float* kpts   = nullptr;
    const int*   eidx   = nullptr;
    const int*   eshift = nullptr;

    for (int i = 0; i < n_in; ++i) {
        switch (in_sizes[i]) {
            case NEDGES * NFEAT: hop    = (const float*)d_in[i]; break;  // 356352
            case NATOMS * NFEAT: ons    = (const float*)d_in[i]; break;  // 22272
            case NKP * 3:        kpts   = (const float*)d_in[i]; break;  // 12
            case 2 * NEDGES:     eidx   = (const int*)d_in[i];   break;  // 12288
            case NEDGES * 3:     eshift = (const int*)d_in[i];   break;  // 18432
            default: break;
        }
    }
    if (!hop || !ons || !kpts || !eidx || !eshift) return;

    if ((long long)out_size == (long long)NCPLX) {
        // f32 real-part output: chain prep + memset fill + per-pair stores.
        k_zero_head<<<NPAIR / 256, 256>>>();
        k_chain<<<(NEDGES + NATOMS + 255) / 256, 256>>>(eidx);
        cudaMemsetAsync(d_out, 0, NCPLX * sizeof(float), 0);
        k_pairs<<<(NPAIR * 32 + 255) / 256, 256>>>(
            hop, ons, kpts, eshift, (float*)d_out);
    } else if ((long long)out_size == 2LL * (long long)NCPLX) {
        hr2hk_zero<<<8192, 256>>>((uint4*)d_out, NCPLX * 8 / 16);
        hr2hk_scatter_cplx<<<NEDGES + NATOMS, 256>>>(
            hop, ons, kpts, eidx, eshift, (float*)d_out);
    }
}